// round 2
// baseline (speedup 1.0000x reference)
#include <cuda_runtime.h>
#include <cstdint>

// KV Q4 dequant, one thread per 32-element quant block:
//   loads 4x int4 (16 packed words), 1 scale, 1 bias
//   stores 8x float4 (32 dequantized fp32)
// Output layout: [ k_dequant flat | v_dequant flat ] (reference reshapes are views)

__global__ __launch_bounds__(256)
void kv_dequant_kernel(const int4* __restrict__ k_packed,
                       const float* __restrict__ k_scale,
                       const float* __restrict__ k_bias,
                       const int4* __restrict__ v_packed,
                       const float* __restrict__ v_scale,
                       const float* __restrict__ v_bias,
                       float4* __restrict__ out,
                       int n_blocks_per_tensor,  // packed words / 16
                       int out_vec_offset_v)     // float4 offset of v region
{
    int tid = blockIdx.x * blockDim.x + threadIdx.x;
    int total = 2 * n_blocks_per_tensor;
    if (tid >= total) return;

    bool is_v = tid >= n_blocks_per_tensor;
    int blk = is_v ? tid - n_blocks_per_tensor : tid;

    const int4*  src = (is_v ? v_packed : k_packed) + (size_t)blk * 4;
    const float* sc  = is_v ? v_scale : k_scale;
    const float* bi  = is_v ? v_bias  : k_bias;

    // Front-batched loads: MLP=4 on the packed data, streaming (read-once)
    int4 w0 = __ldcs(src + 0);
    int4 w1 = __ldcs(src + 1);
    int4 w2 = __ldcs(src + 2);
    int4 w3 = __ldcs(src + 3);
    float s = __ldg(&sc[blk]);
    float b = __ldg(&bi[blk]);

    float4* dst = out + (is_v ? out_vec_offset_v : 0) + (size_t)blk * 8;

    float4 o;
    o.x = (float)(w0.x & 15) * s + b;  o.y = (float)(w0.x >> 4) * s + b;
    o.z = (float)(w0.y & 15) * s + b;  o.w = (float)(w0.y >> 4) * s + b;
    __stcs(dst + 0, o);
    o.x = (float)(w0.z & 15) * s + b;  o.y = (float)(w0.z >> 4) * s + b;
    o.z = (float)(w0.w & 15) * s + b;  o.w = (float)(w0.w >> 4) * s + b;
    __stcs(dst + 1, o);

    o.x = (float)(w1.x & 15) * s + b;  o.y = (float)(w1.x >> 4) * s + b;
    o.z = (float)(w1.y & 15) * s + b;  o.w = (float)(w1.y >> 4) * s + b;
    __stcs(dst + 2, o);
    o.x = (float)(w1.z & 15) * s + b;  o.y = (float)(w1.z >> 4) * s + b;
    o.z = (float)(w1.w & 15) * s + b;  o.w = (float)(w1.w >> 4) * s + b;
    __stcs(dst + 3, o);

    o.x = (float)(w2.x & 15) * s + b;  o.y = (float)(w2.x >> 4) * s + b;
    o.z = (float)(w2.y & 15) * s + b;  o.w = (float)(w2.y >> 4) * s + b;
    __stcs(dst + 4, o);
    o.x = (float)(w2.z & 15) * s + b;  o.y = (float)(w2.z >> 4) * s + b;
    o.z = (float)(w2.w & 15) * s + b;  o.w = (float)(w2.w >> 4) * s + b;
    __stcs(dst + 5, o);

    o.x = (float)(w3.x & 15) * s + b;  o.y = (float)(w3.x >> 4) * s + b;
    o.z = (float)(w3.y & 15) * s + b;  o.w = (float)(w3.y >> 4) * s + b;
    __stcs(dst + 6, o);
    o.x = (float)(w3.z & 15) * s + b;  o.y = (float)(w3.z >> 4) * s + b;
    o.z = (float)(w3.w & 15) * s + b;  o.w = (float)(w3.w >> 4) * s + b;
    __stcs(dst + 7, o);
}

extern "C" void kernel_launch(void* const* d_in, const int* in_sizes, int n_in,
                              void* d_out, int out_size)
{
    // metadata order: k_packed, k_scale, k_bias, v_packed, v_scale, v_bias, batch_size
    const int4*  k_packed = (const int4*) d_in[0];
    const float* k_scale  = (const float*)d_in[1];
    const float* k_bias   = (const float*)d_in[2];
    const int4*  v_packed = (const int4*) d_in[3];
    const float* v_scale  = (const float*)d_in[4];
    const float* v_bias   = (const float*)d_in[5];

    int n_packed_words   = in_sizes[0];            // 4,194,304
    int n_blocks         = n_packed_words / 16;    // 262,144 quant blocks per tensor
    int out_floats_per_t = n_packed_words * 2;     // 8,388,608
    int out_vec_offset_v = out_floats_per_t / 4;   // float4 offset of V region

    int total_threads = 2 * n_blocks;              // 524,288
    int block = 256;
    int grid  = (total_threads + block - 1) / block;

    kv_dequant_kernel<<<grid, block>>>(k_packed, k_scale, k_bias,
                                       v_packed, v_scale, v_bias,
                                       (float4*)d_out,
                                       n_blocks, out_vec_offset_v);
}

// round 5
// speedup vs baseline: 1.7802x; 1.7802x over previous
#include <cuda_runtime.h>
#include <cstdint>

// KV Q4 dequant, one thread per HALF quant block (16 elems):
//   loads 2x int4 (8 packed words), 1 scale, 1 bias   -> MLP=2 on 16B loads
//   stores 4x float4 (16 dequantized fp32)
// Output layout: [ k_dequant flat | v_dequant flat ] (reference reshapes are views)

__global__ __launch_bounds__(256)
void kv_dequant_kernel(const int4* __restrict__ k_packed,
                       const float* __restrict__ k_scale,
                       const float* __restrict__ k_bias,
                       const int4* __restrict__ v_packed,
                       const float* __restrict__ v_scale,
                       const float* __restrict__ v_bias,
                       float4* __restrict__ out,
                       int n_half_per_tensor,   // packed words / 8
                       int out_vec_offset_v)    // float4 offset of v region
{
    int tid = blockIdx.x * blockDim.x + threadIdx.x;
    int total = 2 * n_half_per_tensor;
    if (tid >= total) return;

    bool is_v = tid >= n_half_per_tensor;
    int h = is_v ? tid - n_half_per_tensor : tid;   // half-block index
    int blk = h >> 1;                               // quant-block index

    const int4*  src = (is_v ? v_packed : k_packed) + (size_t)h * 2;
    const float* sc  = is_v ? v_scale : k_scale;
    const float* bi  = is_v ? v_bias  : k_bias;

    // Front-batched: 2x LDG.128 + 2x LDG.32 all in flight together
    int4 w0 = src[0];
    int4 w1 = src[1];
    float s = __ldg(&sc[blk]);
    float b = __ldg(&bi[blk]);

    float4* dst = out + (is_v ? out_vec_offset_v : 0) + (size_t)h * 4;

    float4 o0, o1, o2, o3;
    o0.x = (float)(w0.x & 15) * s + b;  o0.y = (float)(w0.x >> 4) * s + b;
    o0.z = (float)(w0.y & 15) * s + b;  o0.w = (float)(w0.y >> 4) * s + b;
    o1.x = (float)(w0.z & 15) * s + b;  o1.y = (float)(w0.z >> 4) * s + b;
    o1.z = (float)(w0.w & 15) * s + b;  o1.w = (float)(w0.w >> 4) * s + b;
    o2.x = (float)(w1.x & 15) * s + b;  o2.y = (float)(w1.x >> 4) * s + b;
    o2.z = (float)(w1.y & 15) * s + b;  o2.w = (float)(w1.y >> 4) * s + b;
    o3.x = (float)(w1.z & 15) * s + b;  o3.y = (float)(w1.z >> 4) * s + b;
    o3.z = (float)(w1.w & 15) * s + b;  o3.w = (float)(w1.w >> 4) * s + b;

    dst[0] = o0;
    dst[1] = o1;
    dst[2] = o2;
    dst[3] = o3;
}

extern "C" void kernel_launch(void* const* d_in, const int* in_sizes, int n_in,
                              void* d_out, int out_size)
{
    // metadata order: k_packed, k_scale, k_bias, v_packed, v_scale, v_bias, batch_size
    const int4*  k_packed = (const int4*) d_in[0];
    const float* k_scale  = (const float*)d_in[1];
    const float* k_bias   = (const float*)d_in[2];
    const int4*  v_packed = (const int4*) d_in[3];
    const float* v_scale  = (const float*)d_in[4];
    const float* v_bias   = (const float*)d_in[5];

    int n_packed_words   = in_sizes[0];            // 4,194,304
    int n_half           = n_packed_words / 8;     // 524,288 half-blocks per tensor
    int out_floats_per_t = n_packed_words * 2;     // 8,388,608
    int out_vec_offset_v = out_floats_per_t / 4;   // float4 offset of V region

    int total_threads = 2 * n_half;                // 1,048,576
    int block = 256;
    int grid  = (total_threads + block - 1) / block;

    kv_dequant_kernel<<<grid, block>>>(k_packed, k_scale, k_bias,
                                       v_packed, v_scale, v_bias,
                                       (float4*)d_out,
                                       n_half, out_vec_offset_v);
}

// round 10
// speedup vs baseline: 2.2422x; 1.2595x over previous
#include <cuda_runtime.h>
#include <cstdint>

// KV Q4 dequant with TMA bulk stores:
//   - each CTA produces one 16KB output tile in SMEM (dequant via LDG + STS)
//   - one cp.async.bulk (SMEM -> global) per CTA replaces 256 STG.128s,
//     taking the 64MB store stream off the LSU/L1tex path
//   - nibble->float via exponent-bias trick (exact): f = as_float(0x4B000000|n) - 2^23
// Output layout: [ k_dequant flat | v_dequant flat ] (reference reshapes are views)

#define TILE_F4 1024   // float4 per tile = 16KB output, 8KB packed input
#define NTHREADS 256

__global__ __launch_bounds__(NTHREADS)
void kv_dequant_tma(const int2* __restrict__ k_packed,
                    const float* __restrict__ k_scale,
                    const float* __restrict__ k_bias,
                    const int2* __restrict__ v_packed,
                    const float* __restrict__ v_scale,
                    const float* __restrict__ v_bias,
                    float4* __restrict__ out,
                    int tiles_per_tensor,
                    int out_f4_per_tensor)
{
    __shared__ __align__(16) float4 buf[TILE_F4];

    int tile = blockIdx.x;
    bool is_v = tile >= tiles_per_tensor;
    int t = is_v ? tile - tiles_per_tensor : tile;

    const int2*  src = is_v ? v_packed : k_packed;
    const float* sc  = is_v ? v_scale  : k_scale;
    const float* bi  = is_v ? v_bias   : k_bias;

    int base_f4 = t * TILE_F4;            // float4 index of tile start in tensor
    int j0 = threadIdx.x;

    // Front-batched loads: 4x LDG.64 (coalesced: warp covers 256B runs)
    int2 w[4];
    float s[4], b[4];
#pragma unroll
    for (int r = 0; r < 4; r++)
        w[r] = __ldg(&src[base_f4 + j0 + r * NTHREADS]);
#pragma unroll
    for (int r = 0; r < 4; r++) {
        int blk = (base_f4 + j0 + r * NTHREADS) >> 3;  // 8 float4 per quant block
        s[r] = __ldg(&sc[blk]);
        b[r] = __ldg(&bi[blk]);
    }

    const float C = 8388608.0f;  // 2^23
#pragma unroll
    for (int r = 0; r < 4; r++) {
        float4 o;
        // packed word < 256: low nibble = w&15, high nibble = w>>4 (already <=15)
        o.x = (__int_as_float(0x4B000000 | (w[r].x & 15)) - C) * s[r] + b[r];
        o.y = (__int_as_float(0x4B000000 | (w[r].x >> 4)) - C) * s[r] + b[r];
        o.z = (__int_as_float(0x4B000000 | (w[r].y & 15)) - C) * s[r] + b[r];
        o.w = (__int_as_float(0x4B000000 | (w[r].y >> 4)) - C) * s[r] + b[r];
        buf[j0 + r * NTHREADS] = o;   // conflict-free: warp STS.128 contiguous
    }
    __syncthreads();

    if (threadIdx.x == 0) {
        uint32_t saddr = (uint32_t)__cvta_generic_to_shared(buf);
        const float4* gdst = out + (is_v ? out_f4_per_tensor : 0) + base_f4;
        int nbytes = TILE_F4 * 16;
        asm volatile("fence.proxy.async.shared::cta;" ::: "memory");
        asm volatile(
            "cp.async.bulk.global.shared::cta.bulk_group [%0], [%1], %2;"
            :: "l"(gdst), "r"(saddr), "r"(nbytes) : "memory");
        asm volatile("cp.async.bulk.commit_group;" ::: "memory");
        asm volatile("cp.async.bulk.wait_group 0;" ::: "memory");
    }
}

extern "C" void kernel_launch(void* const* d_in, const int* in_sizes, int n_in,
                              void* d_out, int out_size)
{
    // metadata order: k_packed, k_scale, k_bias, v_packed, v_scale, v_bias, batch_size
    const int2*  k_packed = (const int2*) d_in[0];
    const float* k_scale  = (const float*)d_in[1];
    const float* k_bias   = (const float*)d_in[2];
    const int2*  v_packed = (const int2*) d_in[3];
    const float* v_scale  = (const float*)d_in[4];
    const float* v_bias   = (const float*)d_in[5];

    int n_packed_words    = in_sizes[0];             // 4,194,304 words / tensor
    int out_f4_per_tensor = n_packed_words / 2;      // 2,097,152 float4 / tensor
    int tiles_per_tensor  = out_f4_per_tensor / TILE_F4;  // 2048
    int grid = 2 * tiles_per_tensor;                 // 4096 CTAs

    kv_dequant_tma<<<grid, NTHREADS>>>(k_packed, k_scale, k_bias,
                                       v_packed, v_scale, v_bias,
                                       (float4*)d_out,
                                       tiles_per_tensor, out_f4_per_tensor);
}